// round 5
// baseline (speedup 1.0000x reference)
#include <cuda_runtime.h>
#include <cstddef>

#define Bb 64
#define Tt 2048
#define Hh 512
#define Pp 256
#define CHUNKS 8
#define LOG2E 1.4426950408889634f

// ---- device scratch ----
__device__ float g_kq[Bb * Hh];
__device__ float g_bkq[Bb];
__device__ float g_raw[Bb * Tt];
__device__ float g_pm[Bb * 64];
__device__ float g_pz[Bb * 64];
__device__ float g_pacc[(size_t)Bb * 64 * Hh];   // 8 MB partial weighted sums

__device__ __forceinline__ float fexp2(float x) {
    float y;
    asm("ex2.approx.f32 %0, %1;" : "=f"(y) : "f"(x));
    return y;
}

// ---------------------------------------------------------------------------
// Kernel 1 (fused prologue): per batch row b:
//   q = dec[b]@Wq + bq   (512 threads: 2 halves of the d-range per p)
//   bkq[b] = bk . q
//   kq[b,e] = Wk[e,:] . q   (one thread per e, 512-wide)
// ---------------------------------------------------------------------------
__global__ __launch_bounds__(512) void k_qkq(
    const float* __restrict__ dec,
    const float* __restrict__ Wq, const float* __restrict__ bq,
    const float* __restrict__ bk, const float* __restrict__ Wk)
{
    __shared__ float sdec[Hh];
    __shared__ float spart[2][Pp];
    __shared__ float sq[Pp];
    __shared__ float sred[8];
    const int b = blockIdx.x, tid = threadIdx.x;
    const int p = tid & 255, half = tid >> 8;

    sdec[tid] = dec[b * Hh + tid];
    __syncthreads();

    // ---- phase 1: q projection (each thread: 256 of the 512 d's) ----
    {
        const int d_base = half * 256;
        float a0 = 0.f, a1 = 0.f, a2 = 0.f, a3 = 0.f;
#pragma unroll 2
        for (int d0 = 0; d0 < 256; d0 += 16) {
            float w[16];
#pragma unroll
            for (int j = 0; j < 16; j++) w[j] = Wq[(d_base + d0 + j) * Pp + p];
#pragma unroll
            for (int j = 0; j < 16; j += 4) {
                a0 = fmaf(sdec[d_base + d0 + j + 0], w[j + 0], a0);
                a1 = fmaf(sdec[d_base + d0 + j + 1], w[j + 1], a1);
                a2 = fmaf(sdec[d_base + d0 + j + 2], w[j + 2], a2);
                a3 = fmaf(sdec[d_base + d0 + j + 3], w[j + 3], a3);
            }
        }
        spart[half][p] = (a0 + a1) + (a2 + a3);
    }
    __syncthreads();

    if (tid < Pp) {
        const float q = spart[0][tid] + spart[1][tid] + bq[tid];
        sq[tid] = q;
        float r = bk[tid] * q;
#pragma unroll
        for (int o = 16; o; o >>= 1) r += __shfl_xor_sync(0xffffffffu, r, o);
        if ((tid & 31) == 0) sred[tid >> 5] = r;
    }
    __syncthreads();
    if (tid == 0) {
        float s = 0.f;
#pragma unroll
        for (int i = 0; i < 8; i++) s += sred[i];
        g_bkq[b] = s;
    }

    // ---- phase 2: kq[e] = Wk[e,:] . q   (thread = e, float4 stream) ----
    {
        const float4* w4 = (const float4*)(Wk + (size_t)tid * Pp);
        float a0 = 0.f, a1 = 0.f, a2 = 0.f, a3 = 0.f;
#pragma unroll
        for (int p4 = 0; p4 < Pp / 4; p4 += 8) {
            float4 w[8];
#pragma unroll
            for (int j = 0; j < 8; j++) w[j] = w4[p4 + j];
#pragma unroll
            for (int j = 0; j < 8; j++) {
                a0 = fmaf(w[j].x, sq[4 * (p4 + j) + 0], a0);
                a1 = fmaf(w[j].y, sq[4 * (p4 + j) + 1], a1);
                a2 = fmaf(w[j].z, sq[4 * (p4 + j) + 2], a2);
                a3 = fmaf(w[j].w, sq[4 * (p4 + j) + 3], a3);
            }
        }
        g_kq[b * Hh + tid] = (a0 + a1) + (a2 + a3);
    }
}

// ---------------------------------------------------------------------------
// Kernel 2: single HBM streaming pass over encoder_outputs (256 MB).
// Warp-per-timestep, online softmax, register accumulator.
// ---------------------------------------------------------------------------
__global__ __launch_bounds__(256) void k_stream(const float* __restrict__ enc)
{
    const int lane = threadIdx.x & 31;
    const int warp = threadIdx.x >> 5;
    const int b     = blockIdx.x >> 3;
    const int chunk = blockIdx.x & 7;
    const int pid   = (b << 6) | (chunk << 3) | warp;
    const int t0    = chunk * (Tt / CHUNKS) + warp * 32;

    const float4* kq4 = (const float4*)(g_kq + (size_t)b * Hh);
    const float4 k0 = kq4[lane], k1 = kq4[32 + lane],
                 k2 = kq4[64 + lane], k3 = kq4[96 + lane];
    const float bkq = g_bkq[b];

    float4 a0 = {0.f, 0.f, 0.f, 0.f}, a1 = a0, a2 = a0, a3 = a0;
    float m = -3.0e38f, Z = 0.f, myS = 0.f;

    const float4* base = (const float4*)(enc + ((size_t)b * Tt + t0) * Hh);

#pragma unroll 4
    for (int i = 0; i < 32; i++) {
        const float4* row = base + (size_t)i * (Hh / 4);
        float4 v0 = row[lane], v1 = row[32 + lane],
               v2 = row[64 + lane], v3 = row[96 + lane];

        float d;
        d = v0.x * k0.x;
        d = fmaf(v0.y, k0.y, d); d = fmaf(v0.z, k0.z, d); d = fmaf(v0.w, k0.w, d);
        d = fmaf(v1.x, k1.x, d); d = fmaf(v1.y, k1.y, d);
        d = fmaf(v1.z, k1.z, d); d = fmaf(v1.w, k1.w, d);
        d = fmaf(v2.x, k2.x, d); d = fmaf(v2.y, k2.y, d);
        d = fmaf(v2.z, k2.z, d); d = fmaf(v2.w, k2.w, d);
        d = fmaf(v3.x, k3.x, d); d = fmaf(v3.y, k3.y, d);
        d = fmaf(v3.z, k3.z, d); d = fmaf(v3.w, k3.w, d);

        d += __shfl_xor_sync(0xffffffffu, d, 16);
        d += __shfl_xor_sync(0xffffffffu, d, 8);
        d += __shfl_xor_sync(0xffffffffu, d, 4);
        d += __shfl_xor_sync(0xffffffffu, d, 2);
        d += __shfl_xor_sync(0xffffffffu, d, 1);

        const float s = d + bkq;
        if (i == lane) myS = s;

        const float mn   = fmaxf(m, s);
        const float corr = fexp2((m - mn) * LOG2E);
        const float w    = fexp2((s - mn) * LOG2E);
        Z = fmaf(Z, corr, w);
        a0.x = fmaf(a0.x, corr, w * v0.x); a0.y = fmaf(a0.y, corr, w * v0.y);
        a0.z = fmaf(a0.z, corr, w * v0.z); a0.w = fmaf(a0.w, corr, w * v0.w);
        a1.x = fmaf(a1.x, corr, w * v1.x); a1.y = fmaf(a1.y, corr, w * v1.y);
        a1.z = fmaf(a1.z, corr, w * v1.z); a1.w = fmaf(a1.w, corr, w * v1.w);
        a2.x = fmaf(a2.x, corr, w * v2.x); a2.y = fmaf(a2.y, corr, w * v2.y);
        a2.z = fmaf(a2.z, corr, w * v2.z); a2.w = fmaf(a2.w, corr, w * v2.w);
        a3.x = fmaf(a3.x, corr, w * v3.x); a3.y = fmaf(a3.y, corr, w * v3.y);
        a3.z = fmaf(a3.z, corr, w * v3.z); a3.w = fmaf(a3.w, corr, w * v3.w);
        m = mn;
    }

    g_raw[b * Tt + t0 + lane] = myS;
    if (lane == 0) { g_pm[pid] = m; g_pz[pid] = Z; }
    float4* pa = (float4*)(g_pacc + (size_t)pid * Hh);
    pa[lane] = a0; pa[32 + lane] = a1; pa[64 + lane] = a2; pa[96 + lane] = a3;
}

// ---------------------------------------------------------------------------
// Kernel 3: attn epilogue, 512 CTAs (8 per batch row).
// attn[b,t] = exp(raw - mstar)/Z ; mstar/Z recomputed locally (128 floats).
// ---------------------------------------------------------------------------
__global__ __launch_bounds__(256) void k_attn(float* __restrict__ out)
{
    __shared__ float sm[64], sz[64];
    const int b = blockIdx.x >> 3, seg = blockIdx.x & 7, tid = threadIdx.x;

    if (tid < 64) { sm[tid] = g_pm[b * 64 + tid]; sz[tid] = g_pz[b * 64 + tid]; }
    __syncthreads();

    float mstar = -3.0e38f;
#pragma unroll
    for (int i = 0; i < 64; i++) mstar = fmaxf(mstar, sm[i]);
    float Z = 0.f;
#pragma unroll
    for (int i = 0; i < 64; i++) Z += sz[i] * fexp2((sm[i] - mstar) * LOG2E);
    const float invZ = 1.f / Z;

    const int t = seg * 256 + tid;
    out[Bb * Pp + b * Tt + t] =
        fexp2((g_raw[b * Tt + t] - mstar) * LOG2E) * invZ;
}

// ---------------------------------------------------------------------------
// Kernel 4: context: combine 64 partials (one thread per e, 512-wide) then
// Wv GEMV (2 thread-halves of e-range per p).
// ---------------------------------------------------------------------------
__global__ __launch_bounds__(512) void k_ctx(
    const float* __restrict__ Wv, const float* __restrict__ bv,
    float* __restrict__ out)
{
    __shared__ float sm[64], sz[64], ssc[64], sctx[Hh], spart[2][Pp];
    const int b = blockIdx.x, tid = threadIdx.x;

    if (tid < 64) { sm[tid] = g_pm[b * 64 + tid]; sz[tid] = g_pz[b * 64 + tid]; }
    __syncthreads();

    float mstar = -3.0e38f;
#pragma unroll
    for (int i = 0; i < 64; i++) mstar = fmaxf(mstar, sm[i]);
    float Z = 0.f;
#pragma unroll
    for (int i = 0; i < 64; i++) Z += sz[i] * fexp2((sm[i] - mstar) * LOG2E);
    if (tid < 64) ssc[tid] = fexp2((sm[tid] - mstar) * LOG2E);
    __syncthreads();
    const float invZ = 1.f / Z;

    // combine partials: thread = e (512-wide), batched strided loads
    {
        const float* pb = g_pacc + (size_t)b * 64 * Hh + tid;
        float a0 = 0.f, a1 = 0.f, a2 = 0.f, a3 = 0.f;
#pragma unroll
        for (int i = 0; i < 64; i += 8) {
            float v[8];
#pragma unroll
            for (int j = 0; j < 8; j++) v[j] = pb[(size_t)(i + j) * Hh];
#pragma unroll
            for (int j = 0; j < 8; j += 4) {
                a0 = fmaf(v[j + 0], ssc[i + j + 0], a0);
                a1 = fmaf(v[j + 1], ssc[i + j + 1], a1);
                a2 = fmaf(v[j + 2], ssc[i + j + 2], a2);
                a3 = fmaf(v[j + 3], ssc[i + j + 3], a3);
            }
        }
        sctx[tid] = ((a0 + a1) + (a2 + a3)) * invZ;
    }
    __syncthreads();

    // Wv GEMV: thread handles p = tid&255 over half the e-range
    {
        const int p = tid & 255, half = tid >> 8;
        const int e_base = half * 256;
        float a0 = 0.f, a1 = 0.f, a2 = 0.f, a3 = 0.f;
#pragma unroll 2
        for (int e0 = 0; e0 < 256; e0 += 16) {
            float w[16];
#pragma unroll
            for (int j = 0; j < 16; j++) w[j] = Wv[(e_base + e0 + j) * Pp + p];
#pragma unroll
            for (int j = 0; j < 16; j += 4) {
                a0 = fmaf(sctx[e_base + e0 + j + 0], w[j + 0], a0);
                a1 = fmaf(sctx[e_base + e0 + j + 1], w[j + 1], a1);
                a2 = fmaf(sctx[e_base + e0 + j + 2], w[j + 2], a2);
                a3 = fmaf(sctx[e_base + e0 + j + 3], w[j + 3], a3);
            }
        }
        spart[half][p] = (a0 + a1) + (a2 + a3);
    }
    __syncthreads();
    if (tid < Pp)
        out[b * Pp + tid] = spart[0][tid] + spart[1][tid] + bv[tid];
}

// ---------------------------------------------------------------------------
extern "C" void kernel_launch(void* const* d_in, const int* in_sizes, int n_in,
                              void* d_out, int out_size)
{
    const float* dec = (const float*)d_in[0];
    const float* enc = (const float*)d_in[1];
    const float* Wk  = (const float*)d_in[3];
    const float* bk  = (const float*)d_in[4];
    const float* Wv  = (const float*)d_in[5];
    const float* bv  = (const float*)d_in[6];
    const float* Wq  = (const float*)d_in[7];
    const float* bq  = (const float*)d_in[8];
    float* out = (float*)d_out;

    k_qkq<<<Bb, 512>>>(dec, Wq, bq, bk, Wk);
    k_stream<<<Bb * CHUNKS, 256>>>(enc);
    k_attn<<<Bb * CHUNKS, 256>>>(out);
    k_ctx<<<Bb, 512>>>(Wv, bv, out);
}

// round 6
// speedup vs baseline: 1.1722x; 1.1722x over previous
#include <cuda_runtime.h>
#include <cstddef>

#define Bb 64
#define Tt 2048
#define Hh 512
#define Pp 256
#define CHUNKS 8
#define LOG2E 1.4426950408889634f

// ---- device scratch ----
__device__ float g_kq[Bb * Hh];
__device__ float g_bkq[Bb];
__device__ float g_raw[Bb * Tt];
__device__ float g_pz[Bb * CHUNKS];                    // per-CTA exp-sums
__device__ float g_pacc[(size_t)Bb * CHUNKS * Hh];     // per-CTA weighted sums (1 MB)

__device__ __forceinline__ float fexp2(float x) {
    float y;
    asm("ex2.approx.f32 %0, %1;" : "=f"(y) : "f"(x));
    return y;
}

// tree-structured 16-element dot of float4 quads (depth ~5, not 16-serial)
__device__ __forceinline__ float dot16(const float4 v0, const float4 v1,
                                       const float4 v2, const float4 v3,
                                       const float4 k0, const float4 k1,
                                       const float4 k2, const float4 k3)
{
    float p0 = fmaf(v0.y, k0.y, v0.x * k0.x);
    float p1 = fmaf(v0.w, k0.w, v0.z * k0.z);
    float p2 = fmaf(v1.y, k1.y, v1.x * k1.x);
    float p3 = fmaf(v1.w, k1.w, v1.z * k1.z);
    float p4 = fmaf(v2.y, k2.y, v2.x * k2.x);
    float p5 = fmaf(v2.w, k2.w, v2.z * k2.z);
    float p6 = fmaf(v3.y, k3.y, v3.x * k3.x);
    float p7 = fmaf(v3.w, k3.w, v3.z * k3.z);
    return ((p0 + p1) + (p2 + p3)) + ((p4 + p5) + (p6 + p7));
}

// ---------------------------------------------------------------------------
// Kernel 1 (fused prologue) — unchanged from R3/R5.
// ---------------------------------------------------------------------------
__global__ __launch_bounds__(512) void k_qkq(
    const float* __restrict__ dec,
    const float* __restrict__ Wq, const float* __restrict__ bq,
    const float* __restrict__ bk, const float* __restrict__ Wk)
{
    __shared__ float sdec[Hh];
    __shared__ float spart[2][Pp];
    __shared__ float sq[Pp];
    __shared__ float sred[8];
    const int b = blockIdx.x, tid = threadIdx.x;
    const int p = tid & 255, half = tid >> 8;

    sdec[tid] = dec[b * Hh + tid];
    __syncthreads();

    {
        const int d_base = half * 256;
        float a0 = 0.f, a1 = 0.f, a2 = 0.f, a3 = 0.f;
#pragma unroll 2
        for (int d0 = 0; d0 < 256; d0 += 16) {
            float w[16];
#pragma unroll
            for (int j = 0; j < 16; j++) w[j] = Wq[(d_base + d0 + j) * Pp + p];
#pragma unroll
            for (int j = 0; j < 16; j += 4) {
                a0 = fmaf(sdec[d_base + d0 + j + 0], w[j + 0], a0);
                a1 = fmaf(sdec[d_base + d0 + j + 1], w[j + 1], a1);
                a2 = fmaf(sdec[d_base + d0 + j + 2], w[j + 2], a2);
                a3 = fmaf(sdec[d_base + d0 + j + 3], w[j + 3], a3);
            }
        }
        spart[half][p] = (a0 + a1) + (a2 + a3);
    }
    __syncthreads();

    if (tid < Pp) {
        const float q = spart[0][tid] + spart[1][tid] + bq[tid];
        sq[tid] = q;
        float r = bk[tid] * q;
#pragma unroll
        for (int o = 16; o; o >>= 1) r += __shfl_xor_sync(0xffffffffu, r, o);
        if ((tid & 31) == 0) sred[tid >> 5] = r;
    }
    __syncthreads();
    if (tid == 0) {
        float s = 0.f;
#pragma unroll
        for (int i = 0; i < 8; i++) s += sred[i];
        g_bkq[b] = s;
    }

    {
        const float4* w4 = (const float4*)(Wk + (size_t)tid * Pp);
        float a0 = 0.f, a1 = 0.f, a2 = 0.f, a3 = 0.f;
#pragma unroll
        for (int p4 = 0; p4 < Pp / 4; p4 += 8) {
            float4 w[8];
#pragma unroll
            for (int j = 0; j < 8; j++) w[j] = w4[p4 + j];
#pragma unroll
            for (int j = 0; j < 8; j++) {
                a0 = fmaf(w[j].x, sq[4 * (p4 + j) + 0], a0);
                a1 = fmaf(w[j].y, sq[4 * (p4 + j) + 1], a1);
                a2 = fmaf(w[j].z, sq[4 * (p4 + j) + 2], a2);
                a3 = fmaf(w[j].w, sq[4 * (p4 + j) + 3], a3);
            }
        }
        g_kq[b * Hh + tid] = (a0 + a1) + (a2 + a3);
    }
}

// ---------------------------------------------------------------------------
// Kernel 2: streaming pass, FLAT-EXP softmax (no running max), 2 rows per
// body with interleaved shuffle chains, CTA-level smem partial reduction.
// ---------------------------------------------------------------------------
__global__ __launch_bounds__(256, 2) void k_stream(const float* __restrict__ enc)
{
    __shared__ float sacc[8][Hh];   // 16 KB: per-warp acc vectors
    __shared__ float sZ[8];

    const int lane = threadIdx.x & 31;
    const int warp = threadIdx.x >> 5;
    const int b     = blockIdx.x >> 3;
    const int chunk = blockIdx.x & 7;
    const int t0    = chunk * (Tt / CHUNKS) + warp * 32;

    const float4* kq4 = (const float4*)(g_kq + (size_t)b * Hh);
    const float4 k0 = kq4[lane], k1 = kq4[32 + lane],
                 k2 = kq4[64 + lane], k3 = kq4[96 + lane];
    const float bkq = g_bkq[b];

    float4 a0 = {0.f, 0.f, 0.f, 0.f}, a1 = a0, a2 = a0, a3 = a0;
    float Z = 0.f, myS = 0.f;

    const float4* base = (const float4*)(enc + ((size_t)b * Tt + t0) * Hh);

#pragma unroll 2
    for (int i = 0; i < 16; i++) {
        const float4* rA = base + (size_t)(2 * i)     * (Hh / 4);
        const float4* rB = base + (size_t)(2 * i + 1) * (Hh / 4);
        float4 uA0 = rA[lane], uA1 = rA[32 + lane],
               uA2 = rA[64 + lane], uA3 = rA[96 + lane];
        float4 uB0 = rB[lane], uB1 = rB[32 + lane],
               uB2 = rB[64 + lane], uB3 = rB[96 + lane];

        float dA = dot16(uA0, uA1, uA2, uA3, k0, k1, k2, k3);
        float dB = dot16(uB0, uB1, uB2, uB3, k0, k1, k2, k3);

        // interleaved butterfly reductions (two independent chains pipeline)
        dA += __shfl_xor_sync(0xffffffffu, dA, 16);
        dB += __shfl_xor_sync(0xffffffffu, dB, 16);
        dA += __shfl_xor_sync(0xffffffffu, dA, 8);
        dB += __shfl_xor_sync(0xffffffffu, dB, 8);
        dA += __shfl_xor_sync(0xffffffffu, dA, 4);
        dB += __shfl_xor_sync(0xffffffffu, dB, 4);
        dA += __shfl_xor_sync(0xffffffffu, dA, 2);
        dB += __shfl_xor_sync(0xffffffffu, dB, 2);
        dA += __shfl_xor_sync(0xffffffffu, dA, 1);
        dB += __shfl_xor_sync(0xffffffffu, dB, 1);

        const float sA = dA + bkq;
        const float sB = dB + bkq;
        if (2 * i     == lane) myS = sA;
        if (2 * i + 1 == lane) myS = sB;

        const float wA = fexp2(sA * LOG2E);   // flat exp — no max subtraction
        const float wB = fexp2(sB * LOG2E);
        Z += wA + wB;
        a0.x = fmaf(wA, uA0.x, fmaf(wB, uB0.x, a0.x));
        a0.y = fmaf(wA, uA0.y, fmaf(wB, uB0.y, a0.y));
        a0.z = fmaf(wA, uA0.z, fmaf(wB, uB0.z, a0.z));
        a0.w = fmaf(wA, uA0.w, fmaf(wB, uB0.w, a0.w));
        a1.x = fmaf(wA, uA1.x, fmaf(wB, uB1.x, a1.x));
        a1.y = fmaf(wA, uA1.y, fmaf(wB, uB1.y, a1.y));
        a1.z = fmaf(wA, uA1.z, fmaf(wB, uB1.z, a1.z));
        a1.w = fmaf(wA, uA1.w, fmaf(wB, uB1.w, a1.w));
        a2.x = fmaf(wA, uA2.x, fmaf(wB, uB2.x, a2.x));
        a2.y = fmaf(wA, uA2.y, fmaf(wB, uB2.y, a2.y));
        a2.z = fmaf(wA, uA2.z, fmaf(wB, uB2.z, a2.z));
        a2.w = fmaf(wA, uA2.w, fmaf(wB, uB2.w, a2.w));
        a3.x = fmaf(wA, uA3.x, fmaf(wB, uB3.x, a3.x));
        a3.y = fmaf(wA, uA3.y, fmaf(wB, uB3.y, a3.y));
        a3.z = fmaf(wA, uA3.z, fmaf(wB, uB3.z, a3.z));
        a3.w = fmaf(wA, uA3.w, fmaf(wB, uB3.w, a3.w));
    }

    g_raw[b * Tt + t0 + lane] = myS;

    // CTA reduction: partials are purely additive under flat exp
    float4* sa = (float4*)sacc[warp];
    sa[lane] = a0; sa[32 + lane] = a1; sa[64 + lane] = a2; sa[96 + lane] = a3;
    if (lane == 0) sZ[warp] = Z;
    __syncthreads();

    const int pid = blockIdx.x;     // b*8 + chunk
    if (threadIdx.x < 128) {        // 128 float4s = 512 floats
        float4 s = {0.f, 0.f, 0.f, 0.f};
#pragma unroll
        for (int w = 0; w < 8; w++) {
            float4 v = ((const float4*)sacc[w])[threadIdx.x];
            s.x += v.x; s.y += v.y; s.z += v.z; s.w += v.w;
        }
        ((float4*)(g_pacc + (size_t)pid * Hh))[threadIdx.x] = s;
    } else if (threadIdx.x == 128) {
        float z = 0.f;
#pragma unroll
        for (int w = 0; w < 8; w++) z += sZ[w];
        g_pz[pid] = z;
    }
}

// ---------------------------------------------------------------------------
// Kernel 3: attn epilogue, 512 CTAs. attn = exp(raw)/Z_total.
// ---------------------------------------------------------------------------
__global__ __launch_bounds__(256) void k_attn(float* __restrict__ out)
{
    const int b = blockIdx.x >> 3, seg = blockIdx.x & 7, tid = threadIdx.x;

    float Z = 0.f;
#pragma unroll
    for (int i = 0; i < CHUNKS; i++) Z += g_pz[b * CHUNKS + i];
    const float invZ = 1.f / Z;

    const int t = seg * 256 + tid;
    out[Bb * Pp + b * Tt + t] = fexp2(g_raw[b * Tt + t] * LOG2E) * invZ;
}

// ---------------------------------------------------------------------------
// Kernel 4: context: sum 8 per-CTA partials, divide by Z, Wv GEMV.
// ---------------------------------------------------------------------------
__global__ __launch_bounds__(512) void k_ctx(
    const float* __restrict__ Wv, const float* __restrict__ bv,
    float* __restrict__ out)
{
    __shared__ float sctx[Hh], spart[2][Pp];
    const int b = blockIdx.x, tid = threadIdx.x;

    float Z = 0.f;
#pragma unroll
    for (int i = 0; i < CHUNKS; i++) Z += g_pz[b * CHUNKS + i];
    const float invZ = 1.f / Z;

    // combine 8 partials (thread = e)
    {
        const float* pb = g_pacc + (size_t)b * CHUNKS * Hh + tid;
        float v[CHUNKS];
#pragma unroll
        for (int w = 0; w < CHUNKS; w++) v[w] = pb[(size_t)w * Hh];
        float s = 0.f;
#pragma unroll
        for (int w = 0; w < CHUNKS; w++) s += v[w];
        sctx[tid] = s * invZ;
    }
    __syncthreads();

    // Wv GEMV: p = tid&255 over half the e-range
    {
        const int p = tid & 255, half = tid >> 8;
        const int e_base = half * 256;
        float a0 = 0.f, a1 = 0.f, a2 = 0.f, a3 = 0.f;
#pragma unroll 2
        for (int e0 = 0; e0 < 256; e0 += 16) {
            float w[16];
#pragma unroll
            for (int j = 0; j < 16; j++) w[j] = Wv[(e_base + e0 + j) * Pp + p];
#pragma unroll
            for (int j = 0; j < 16; j += 4) {
                a0 = fmaf(sctx[e_base + e0 + j + 0], w[j + 0], a0);
                a1 = fmaf(sctx[e_base + e0 + j + 1], w[j + 1], a1);
                a2 = fmaf(sctx[e_base + e0 + j + 2], w[j + 2], a2);
                a3 = fmaf(sctx[e_base + e0 + j + 3], w[j + 3], a3);
            }
        }
        spart[half][p] = (a0 + a1) + (a2 + a3);
    }
    __syncthreads();
    if (tid < Pp)
        out[b * Pp + tid] = spart[0][tid] + spart[1][tid] + bv[tid];
}

// ---------------------------------------------------------------------------
extern "C" void kernel_launch(void* const* d_in, const int* in_sizes, int n_in,
                              void* d_out, int out_size)
{
    const float* dec = (const float*)d_in[0];
    const float* enc = (const float*)d_in[1];
    const float* Wk  = (const float*)d_in[3];
    const float* bk  = (const float*)d_in[4];
    const float* Wv  = (const float*)d_in[5];
    const float* bv  = (const float*)d_in[6];
    const float* Wq  = (const float*)d_in[7];
    const float* bq  = (const float*)d_in[8];
    float* out = (float*)d_out;

    k_qkq<<<Bb, 512>>>(dec, Wq, bq, bk, Wk);
    k_stream<<<Bb * CHUNKS, 256>>>(enc);
    k_attn<<<Bb * CHUNKS, 256>>>(out);
    k_ctx<<<Bb, 512>>>(Wv, bv, out);
}

// round 7
// speedup vs baseline: 1.5148x; 1.2923x over previous
#include <cuda_runtime.h>
#include <cstddef>

#define Bb 64
#define Tt 2048
#define Hh 512
#define Pp 256
#define CHUNKS 4      // stream CTAs per batch row (256 CTAs total, 1 wave @2/SM)
#define LOG2E 1.4426950408889634f

// ---- device scratch ----
__device__ float g_qpart[Bb * 8 * Pp];                 // q partials (512 KB)
__device__ float g_q[Bb * Pp];
__device__ float g_kq[Bb * Hh];
__device__ float g_bkq[Bb];
__device__ float g_raw[Bb * Tt];
__device__ float g_pz[Bb * CHUNKS];
__device__ float g_pacc[(size_t)Bb * CHUNKS * Hh];     // per-CTA weighted sums (512 KB)
__device__ float g_cpart[Bb * 8 * Pp];                 // ctx@Wv partials (512 KB)

__device__ __forceinline__ float fexp2(float x) {
    float y;
    asm("ex2.approx.f32 %0, %1;" : "=f"(y) : "f"(x));
    return y;
}

__device__ __forceinline__ float dot16(const float4 v0, const float4 v1,
                                       const float4 v2, const float4 v3,
                                       const float4 k0, const float4 k1,
                                       const float4 k2, const float4 k3)
{
    float p0 = fmaf(v0.y, k0.y, v0.x * k0.x);
    float p1 = fmaf(v0.w, k0.w, v0.z * k0.z);
    float p2 = fmaf(v1.y, k1.y, v1.x * k1.x);
    float p3 = fmaf(v1.w, k1.w, v1.z * k1.z);
    float p4 = fmaf(v2.y, k2.y, v2.x * k2.x);
    float p5 = fmaf(v2.w, k2.w, v2.z * k2.z);
    float p6 = fmaf(v3.y, k3.y, v3.x * k3.x);
    float p7 = fmaf(v3.w, k3.w, v3.z * k3.z);
    return ((p0 + p1) + (p2 + p3)) + ((p4 + p5) + (p6 + p7));
}

// ---------------------------------------------------------------------------
// K1: q partials. grid (8 e-chunks, 64 b) x 256. Thread p: 64-term partial
// dot over its e-chunk (4 load batches of 16 -> low latency exposure).
// ---------------------------------------------------------------------------
__global__ __launch_bounds__(256) void k_qpart(
    const float* __restrict__ dec, const float* __restrict__ Wq)
{
    __shared__ float sdec[64];
    const int ec = blockIdx.x, b = blockIdx.y, p = threadIdx.x;
    const int e0 = ec * 64;

    if (p < 64) sdec[p] = dec[b * Hh + e0 + p];
    __syncthreads();

    float a0 = 0.f, a1 = 0.f, a2 = 0.f, a3 = 0.f;
#pragma unroll
    for (int j0 = 0; j0 < 64; j0 += 16) {
        float w[16];
#pragma unroll
        for (int j = 0; j < 16; j++) w[j] = Wq[(e0 + j0 + j) * Pp + p];
#pragma unroll
        for (int j = 0; j < 16; j += 4) {
            a0 = fmaf(sdec[j0 + j + 0], w[j + 0], a0);
            a1 = fmaf(sdec[j0 + j + 1], w[j + 1], a1);
            a2 = fmaf(sdec[j0 + j + 2], w[j + 2], a2);
            a3 = fmaf(sdec[j0 + j + 3], w[j + 3], a3);
        }
    }
    g_qpart[(b * 8 + ec) * Pp + p] = (a0 + a1) + (a2 + a3);
}

// ---------------------------------------------------------------------------
// K2: q = sum partials + bq ; bkq = bk . q.  grid 64 x 256.
// ---------------------------------------------------------------------------
__global__ __launch_bounds__(256) void k_qsum(
    const float* __restrict__ bq, const float* __restrict__ bk)
{
    __shared__ float sred[8];
    const int b = blockIdx.x, p = threadIdx.x;

    float q = bq[p];
#pragma unroll
    for (int c = 0; c < 8; c++) q += g_qpart[(b * 8 + c) * Pp + p];
    g_q[b * Pp + p] = q;

    float r = bk[p] * q;
#pragma unroll
    for (int o = 16; o; o >>= 1) r += __shfl_xor_sync(0xffffffffu, r, o);
    if ((p & 31) == 0) sred[p >> 5] = r;
    __syncthreads();
    if (p == 0) {
        float s = 0.f;
#pragma unroll
        for (int i = 0; i < 8; i++) s += sred[i];
        g_bkq[b] = s;
    }
}

// ---------------------------------------------------------------------------
// K3: kq[b,e] = Wk[e,:] . q[b].  grid (4 e-chunks, 64 b) x 128, thread = e.
// ---------------------------------------------------------------------------
__global__ __launch_bounds__(128) void k_kq(const float* __restrict__ Wk)
{
    __shared__ float sq[Pp];
    const int b = blockIdx.y, tid = threadIdx.x;
    const int e = blockIdx.x * 128 + tid;

    sq[tid]       = g_q[b * Pp + tid];
    sq[tid + 128] = g_q[b * Pp + 128 + tid];
    __syncthreads();

    const float4* w4 = (const float4*)(Wk + (size_t)e * Pp);
    float a0 = 0.f, a1 = 0.f, a2 = 0.f, a3 = 0.f;
#pragma unroll
    for (int p4 = 0; p4 < Pp / 4; p4 += 8) {
        float4 w[8];
#pragma unroll
        for (int j = 0; j < 8; j++) w[j] = w4[p4 + j];
#pragma unroll
        for (int j = 0; j < 8; j++) {
            a0 = fmaf(w[j].x, sq[4 * (p4 + j) + 0], a0);
            a1 = fmaf(w[j].y, sq[4 * (p4 + j) + 1], a1);
            a2 = fmaf(w[j].z, sq[4 * (p4 + j) + 2], a2);
            a3 = fmaf(w[j].w, sq[4 * (p4 + j) + 3], a3);
        }
    }
    g_kq[b * Hh + e] = (a0 + a1) + (a2 + a3);
}

// ---------------------------------------------------------------------------
// K4: streaming pass (256 MB). 256 CTAs (single wave @ 2/SM), 8 warps,
// 64 timesteps per warp in two 32-row groups. Flat-exp softmax, 2-row
// interleaved body, CTA-level smem partial reduction.
// ---------------------------------------------------------------------------
__global__ __launch_bounds__(256, 2) void k_stream(const float* __restrict__ enc)
{
    __shared__ float sacc[8][Hh];
    __shared__ float sZ[8];

    const int lane = threadIdx.x & 31;
    const int warp = threadIdx.x >> 5;
    const int b     = blockIdx.x >> 2;       // / CHUNKS
    const int chunk = blockIdx.x & 3;
    const int t0    = chunk * (Tt / CHUNKS) + warp * 64;

    const float4* kq4 = (const float4*)(g_kq + (size_t)b * Hh);
    const float4 k0 = kq4[lane], k1 = kq4[32 + lane],
                 k2 = kq4[64 + lane], k3 = kq4[96 + lane];
    const float bkq = g_bkq[b];

    float4 a0 = {0.f, 0.f, 0.f, 0.f}, a1 = a0, a2 = a0, a3 = a0;
    float Z = 0.f;

#pragma unroll
    for (int grp = 0; grp < 2; grp++) {
        const float4* base =
            (const float4*)(enc + ((size_t)b * Tt + t0 + grp * 32) * Hh);
        float myS = 0.f;

#pragma unroll 2
        for (int i = 0; i < 16; i++) {
            const float4* rA = base + (size_t)(2 * i)     * (Hh / 4);
            const float4* rB = base + (size_t)(2 * i + 1) * (Hh / 4);
            float4 uA0 = rA[lane], uA1 = rA[32 + lane],
                   uA2 = rA[64 + lane], uA3 = rA[96 + lane];
            float4 uB0 = rB[lane], uB1 = rB[32 + lane],
                   uB2 = rB[64 + lane], uB3 = rB[96 + lane];

            float dA = dot16(uA0, uA1, uA2, uA3, k0, k1, k2, k3);
            float dB = dot16(uB0, uB1, uB2, uB3, k0, k1, k2, k3);

            dA += __shfl_xor_sync(0xffffffffu, dA, 16);
            dB += __shfl_xor_sync(0xffffffffu, dB, 16);
            dA += __shfl_xor_sync(0xffffffffu, dA, 8);
            dB += __shfl_xor_sync(0xffffffffu, dB, 8);
            dA += __shfl_xor_sync(0xffffffffu, dA, 4);
            dB += __shfl_xor_sync(0xffffffffu, dB, 4);
            dA += __shfl_xor_sync(0xffffffffu, dA, 2);
            dB += __shfl_xor_sync(0xffffffffu, dB, 2);
            dA += __shfl_xor_sync(0xffffffffu, dA, 1);
            dB += __shfl_xor_sync(0xffffffffu, dB, 1);

            const float sA = dA + bkq;
            const float sB = dB + bkq;
            if (2 * i     == lane) myS = sA;
            if (2 * i + 1 == lane) myS = sB;

            const float wA = fexp2(sA * LOG2E);
            const float wB = fexp2(sB * LOG2E);
            Z += wA + wB;
            a0.x = fmaf(wA, uA0.x, fmaf(wB, uB0.x, a0.x));
            a0.y = fmaf(wA, uA0.y, fmaf(wB, uB0.y, a0.y));
            a0.z = fmaf(wA, uA0.z, fmaf(wB, uB0.z, a0.z));
            a0.w = fmaf(wA, uA0.w, fmaf(wB, uB0.w, a0.w));
            a1.x = fmaf(wA, uA1.x, fmaf(wB, uB1.x, a1.x));
            a1.y = fmaf(wA, uA1.y, fmaf(wB, uB1.y, a1.y));
            a1.z = fmaf(wA, uA1.z, fmaf(wB, uB1.z, a1.z));
            a1.w = fmaf(wA, uA1.w, fmaf(wB, uB1.w, a1.w));
            a2.x = fmaf(wA, uA2.x, fmaf(wB, uB2.x, a2.x));
            a2.y = fmaf(wA, uA2.y, fmaf(wB, uB2.y, a2.y));
            a2.z = fmaf(wA, uA2.z, fmaf(wB, uB2.z, a2.z));
            a2.w = fmaf(wA, uA2.w, fmaf(wB, uB2.w, a2.w));
            a3.x = fmaf(wA, uA3.x, fmaf(wB, uB3.x, a3.x));
            a3.y = fmaf(wA, uA3.y, fmaf(wB, uB3.y, a3.y));
            a3.z = fmaf(wA, uA3.z, fmaf(wB, uB3.z, a3.z));
            a3.w = fmaf(wA, uA3.w, fmaf(wB, uB3.w, a3.w));
        }
        g_raw[b * Tt + t0 + grp * 32 + lane] = myS;
    }

    // CTA reduction (partials purely additive under flat exp)
    float4* sa = (float4*)sacc[warp];
    sa[lane] = a0; sa[32 + lane] = a1; sa[64 + lane] = a2; sa[96 + lane] = a3;
    if (lane == 0) sZ[warp] = Z;
    __syncthreads();

    const int pid = blockIdx.x;        // b*CHUNKS + chunk
    if (threadIdx.x < 128) {
        float4 s = {0.f, 0.f, 0.f, 0.f};
#pragma unroll
        for (int w = 0; w < 8; w++) {
            float4 v = ((const float4*)sacc[w])[threadIdx.x];
            s.x += v.x; s.y += v.y; s.z += v.z; s.w += v.w;
        }
        ((float4*)(g_pacc + (size_t)pid * Hh))[threadIdx.x] = s;
    } else if (threadIdx.x == 128) {
        float z = 0.f;
#pragma unroll
        for (int w = 0; w < 8; w++) z += sZ[w];
        g_pz[pid] = z;
    }
}

// ---------------------------------------------------------------------------
// K5: attn epilogue, 512 CTAs. attn = exp(raw)/Z.
// ---------------------------------------------------------------------------
__global__ __launch_bounds__(256) void k_attn(float* __restrict__ out)
{
    const int b = blockIdx.x >> 3, seg = blockIdx.x & 7, tid = threadIdx.x;

    float Z = 0.f;
#pragma unroll
    for (int i = 0; i < CHUNKS; i++) Z += g_pz[b * CHUNKS + i];
    const float invZ = 1.f / Z;

    const int t = seg * 256 + tid;
    out[Bb * Pp + b * Tt + t] = fexp2(g_raw[b * Tt + t] * LOG2E) * invZ;
}

// ---------------------------------------------------------------------------
// K6: ctx@Wv partials. grid (8 e-chunks, 64 b) x 256. Fuses partial-combine
// (4 adds per e) with the 64-term Wv partial GEMV.
// ---------------------------------------------------------------------------
__global__ __launch_bounds__(256) void k_cpart(const float* __restrict__ Wv)
{
    __shared__ float ssctx[64];
    const int ec = blockIdx.x, b = blockIdx.y, p = threadIdx.x;
    const int e0 = ec * 64;

    float Z = 0.f;
#pragma unroll
    for (int i = 0; i < CHUNKS; i++) Z += g_pz[b * CHUNKS + i];
    const float invZ = 1.f / Z;

    if (p < 64) {
        const int e = e0 + p;
        float s = 0.f;
#pragma unroll
        for (int c = 0; c < CHUNKS; c++)
            s += g_pacc[(size_t)(b * CHUNKS + c) * Hh + e];
        ssctx[p] = s * invZ;
    }
    __syncthreads();

    float a0 = 0.f, a1 = 0.f, a2 = 0.f, a3 = 0.f;
#pragma unroll
    for (int j0 = 0; j0 < 64; j0 += 16) {
        float w[16];
#pragma unroll
        for (int j = 0; j < 16; j++) w[j] = Wv[(e0 + j0 + j) * Pp + p];
#pragma unroll
        for (int j = 0; j < 16; j += 4) {
            a0 = fmaf(ssctx[j0 + j + 0], w[j + 0], a0);
            a1 = fmaf(ssctx[j0 + j + 1], w[j + 1], a1);
            a2 = fmaf(ssctx[j0 + j + 2], w[j + 2], a2);
            a3 = fmaf(ssctx[j0 + j + 3], w[j + 3], a3);
        }
    }
    g_cpart[(b * 8 + ec) * Pp + p] = (a0 + a1) + (a2 + a3);
}

// ---------------------------------------------------------------------------
// K7: context = sum partials + bv.  grid 64 x 256.
// ---------------------------------------------------------------------------
__global__ __launch_bounds__(256) void k_csum(
    const float* __restrict__ bv, float* __restrict__ out)
{
    const int b = blockIdx.x, p = threadIdx.x;
    float c = bv[p];
#pragma unroll
    for (int i = 0; i < 8; i++) c += g_cpart[(b * 8 + i) * Pp + p];
    out[b * Pp + p] = c;
}

// ---------------------------------------------------------------------------
extern "C" void kernel_launch(void* const* d_in, const int* in_sizes, int n_in,
                              void* d_out, int out_size)
{
    const float* dec = (const float*)d_in[0];
    const float* enc = (const float*)d_in[1];
    const float* Wk  = (const float*)d_in[3];
    const float* bk  = (const float*)d_in[4];
    const float* Wv  = (const float*)d_in[5];
    const float* bv  = (const float*)d_in[6];
    const float* Wq  = (const float*)d_in[7];
    const float* bq  = (const float*)d_in[8];
    float* out = (float*)d_out;

    k_qpart<<<dim3(8, Bb), 256>>>(dec, Wq);
    k_qsum<<<Bb, 256>>>(bq, bk);
    k_kq<<<dim3(4, Bb), 128>>>(Wk);
    k_stream<<<Bb * CHUNKS, 256>>>(enc);
    k_attn<<<Bb * 8, 256>>>(out);
    k_cpart<<<dim3(8, Bb), 256>>>(Wv);
    k_csum<<<Bb, 256>>>(bv, out);
}